// round 12
// baseline (speedup 1.0000x reference)
#include <cuda_runtime.h>
#include <cuda_bf16.h>
#include <cuda_fp16.h>
#include <math_constants.h>
#include <cstdint>

// Problem dims (fixed by setup_inputs)
constexpr int NP = 32768;   // 8*4096 points
constexpr int KC = 2048;    // codebook size
constexpr int D  = 128;     // dim
constexpr float LEPS = 1e-6f;
constexpr float OFFS = 128.0f;        // recenters S ~ -128+-28 to ~0 for fp16 storage
// Scores stored pre-scaled: S' = (S + OFFS) * SCALE, SCALE = log2(e)/T.
// Softmax prob = 2^(v' - m') (one ex2 per element; T and log2e pre-folded).
constexpr float SCALE = 1.4426950408889634f / 0.9f;   // 1.60299449
constexpr float RESCUE_THR_S = 0.5f * SCALE;          // raw 0.5 margin, scaled domain
constexpr int STRIPE = NP / 2;        // 16384 rows -> 64 MB score slab (fits L2)

// Scratch (__device__ globals; no allocation allowed)
__device__ __half g_scores16[(size_t)NP * KC];         // 128 MB score matrix (scaled)
__device__ float g_esq[KC];                            // ||e_k||^2 (exact, for rescue)
__device__ float g_esqc[KC];                           // (OFFS - esq) * SCALE (epilogue)
__device__ __nv_bfloat16 g_Xs[(size_t)NP * 128];       // bf16(x) (8 MB)
__device__ __nv_bfloat16 g_Es[(size_t)KC * 256];       // 2-way bf16 split of embed
__device__ float g_part[(size_t)(NP / 32) * KC];       // per-block class-prob partials
__device__ float g_part2[16 * KC];                     // stage-1 reduced partials
__device__ float g_acc[KC];                            // class sums

// ---------------------------------------------------------------------------
__device__ __forceinline__ uint32_t smem_u32(const void* p) {
    uint32_t a;
    asm("{ .reg .u64 t; cvta.to.shared.u64 t, %1; cvt.u32.u64 %0, t; }" : "=r"(a) : "l"(p));
    return a;
}
__device__ __forceinline__ uint32_t sw128(uint32_t off) { return off ^ ((off >> 3) & 0x70); }
__device__ __forceinline__ float ex2f(float x) {
    float r;
    asm("ex2.approx.f32 %0, %1;" : "=f"(r) : "f"(x));
    return r;
}

__device__ __forceinline__ void cp_async16(uint32_t saddr, const void* gaddr) {
    asm volatile("cp.async.cg.shared.global [%0], [%1], 16;" :: "r"(saddr), "l"(gaddr));
}
#define CP_COMMIT() asm volatile("cp.async.commit_group;" ::: "memory")
#define CP_WAIT(n)  asm volatile("cp.async.wait_group %0;" :: "n"(n) : "memory")

__device__ __forceinline__ void ldm_x4(uint32_t* a, uint32_t addr) {
    asm volatile("ldmatrix.sync.aligned.m8n8.x4.shared.b16 {%0,%1,%2,%3}, [%4];"
                 : "=r"(a[0]), "=r"(a[1]), "=r"(a[2]), "=r"(a[3]) : "r"(addr));
}
__device__ __forceinline__ void mma_bf16(float* c, const uint32_t* a, const uint32_t* b) {
    asm volatile("mma.sync.aligned.m16n8k16.row.col.f32.bf16.bf16.f32 "
                 "{%0,%1,%2,%3}, {%4,%5,%6,%7}, {%8,%9}, {%0,%1,%2,%3};"
                 : "+f"(c[0]), "+f"(c[1]), "+f"(c[2]), "+f"(c[3])
                 : "r"(a[0]), "r"(a[1]), "r"(a[2]), "r"(a[3]), "r"(b[0]), "r"(b[1]));
}

// ---------------------------------------------------------------------------
// Kernel 0: bf16 conversion of x; 2-way bf16 split of embed
// ---------------------------------------------------------------------------
__global__ __launch_bounds__(256) void split_kernel(const float* __restrict__ x,
                                                    const float* __restrict__ e) {
    int i = blockIdx.x * 256 + threadIdx.x;
    if (i < NP * D) {
        g_Xs[i] = __float2bfloat16(x[i]);
    } else {
        int j = i - NP * D;
        if (j >= KC * D) return;
        float v = e[j];
        int c = j & (D - 1);
        __nv_bfloat16* dst = g_Es + (size_t)(j >> 7) * 256;
        __nv_bfloat16 b0 = __float2bfloat16(v);
        float r1 = v - __bfloat162float(b0);
        __nv_bfloat16 b1 = __float2bfloat16(r1);
        dst[c] = b0; dst[128 + c] = b1;
    }
}

// ---------------------------------------------------------------------------
// Kernel 1: e_sq (exact) + scaled epilogue constant
// ---------------------------------------------------------------------------
__global__ void prep_kernel(const float* __restrict__ embed) {
    int k = blockIdx.x * blockDim.x + threadIdx.x;
    if (k < KC) {
        const float4* e = (const float4*)(embed + (size_t)k * D);
        float s = 0.f;
#pragma unroll
        for (int i = 0; i < D / 4; i++) {
            float4 v = e[i];
            s += v.x * v.x + v.y * v.y + v.z * v.z + v.w * v.w;
        }
        g_esq[k] = s;
        g_esqc[k] = (OFFS - s) * SCALE;
    }
}

// ---------------------------------------------------------------------------
// Kernel 2: mma.sync bf16 GEMM  S16 = fp16((2*x0*(e0+e1) - e_sq + OFFS)*SCALE)
// Block 256 thr (8 warps), tile M128 x N128, warp tile 32x64.
// 4 K-chunks of 64 (virtual K=256), 3-stage cp.async, 1 barrier per chunk.
// Stripe offset m0 selects the 16K-row half being produced.
// ---------------------------------------------------------------------------
constexpr int STG_SZ = 128 * 128;                 // 16 KB per operand stage
constexpr int GEMM_SMEM = 3 * 2 * STG_SZ;         // 98304 B (>= 66048 epilogue tile)

__global__ __launch_bounds__(256, 2) void gemm_kernel(int m0) {
    extern __shared__ char smem[];
    const uint32_t sb = smem_u32(smem);
    const int tid = threadIdx.x, wid = tid >> 5, lane = tid & 31;
    const int warp_m = wid & 3, warp_n = wid >> 2;
    const int bm = m0 + blockIdx.y * 128, bn = blockIdx.x * 128;

    float acc[2][8][4];
#pragma unroll
    for (int mt = 0; mt < 2; mt++)
#pragma unroll
        for (int nt = 0; nt < 8; nt++)
#pragma unroll
            for (int q = 0; q < 4; q++) acc[mt][nt][q] = 0.f;

    const int lr = tid >> 1;                 // rows 0..127 (2 threads/row)
    const int ls0 = (tid & 1) * 4;           // 16B segment base

    // A x4: 16 rows x 32B
    const int arow = warp_m * 32 + (lane & 7) + ((lane >> 3) & 1) * 8;
    const int acol = ((lane >> 4) & 1) * 16;
    // B x4 (two paired 8-row n-tiles)
    const int b_lrow = ((lane >> 4) & 1) * 8 + (lane & 7);
    const int b_lcol = ((lane >> 3) & 1) * 16;

    // chunk c: p = c>>1 selects e0/e1, h = c&1 selects 64-dim half.
    auto issue_chunk = [&](int c, int stage) {
        const int p = c >> 1, h = c & 1;
        const uint32_t sa = sb + stage * 2 * STG_SZ;
        const uint32_t sbB = sa + STG_SZ;
        const __nv_bfloat16* ga = g_Xs + (size_t)(bm + lr) * 128 + h * 64;
        const __nv_bfloat16* gb = g_Es + (size_t)(bn + lr) * 256 + p * 128 + h * 64;
#pragma unroll
        for (int s = 0; s < 4; s++) {
            cp_async16(sa + sw128((uint32_t)lr * 128 + (ls0 + s) * 16), ga + (ls0 + s) * 8);
            cp_async16(sbB + sw128((uint32_t)lr * 128 + (ls0 + s) * 16), gb + (ls0 + s) * 8);
        }
        CP_COMMIT();
    };

    issue_chunk(0, 0);
    issue_chunk(1, 1);

#pragma unroll 1
    for (int c = 0; c < 4; c++) {
        const int stage = c % 3;
        if (c < 3) { CP_WAIT(1); } else { CP_WAIT(0); }
        __syncthreads();

        const uint32_t sa = sb + stage * 2 * STG_SZ;
        const uint32_t sbB = sa + STG_SZ;
#pragma unroll
        for (int ks = 0; ks < 4; ks++) {
            uint32_t a[2][4];
#pragma unroll
            for (int mt = 0; mt < 2; mt++)
                ldm_x4(a[mt], sa + sw128((uint32_t)(arow + mt * 16) * 128 + ks * 32 + acol));
#pragma unroll
            for (int ntp = 0; ntp < 4; ntp++) {
                uint32_t b[4];
                ldm_x4(b, sbB + sw128((uint32_t)(warp_n * 64 + ntp * 16 + b_lrow) * 128
                                       + ks * 32 + b_lcol));
                mma_bf16(acc[0][2 * ntp],     a[0], b);
                mma_bf16(acc[1][2 * ntp],     a[1], b);
                mma_bf16(acc[0][2 * ntp + 1], a[0], b + 2);
                mma_bf16(acc[1][2 * ntp + 1], a[1], b + 2);
            }
        }
        if (c <= 1) issue_chunk(c + 2, (c + 2) % 3);
    }
    __syncthreads();

    // Epilogue: accum -> padded smem tile -> coalesced fp16 scaled scores
    float* tile = (float*)smem;
#pragma unroll
    for (int mt = 0; mt < 2; mt++) {
        const int r = warp_m * 32 + mt * 16 + (lane >> 2);
#pragma unroll
        for (int nt = 0; nt < 8; nt++) {
            const int cb = warp_n * 64 + nt * 8 + 2 * (lane & 3);
            tile[r * 129 + cb]           = acc[mt][nt][0];
            tile[r * 129 + cb + 1]       = acc[mt][nt][1];
            tile[(r + 8) * 129 + cb]     = acc[mt][nt][2];
            tile[(r + 8) * 129 + cb + 1] = acc[mt][nt][3];
        }
    }
    __syncthreads();

    constexpr float S2 = 2.0f * SCALE;
#pragma unroll
    for (int i = 0; i < 16; i++) {
        const int lin = tid + i * 256;           // 0..4095
        const int row = lin >> 5;
        const int c4 = (lin & 31) * 4;
        const float4 ec = *(const float4*)(g_esqc + bn + c4);
        const float sx = fmaf(tile[row * 129 + c4 + 0], S2, ec.x);
        const float sy = fmaf(tile[row * 129 + c4 + 1], S2, ec.y);
        const float sz = fmaf(tile[row * 129 + c4 + 2], S2, ec.z);
        const float sw = fmaf(tile[row * 129 + c4 + 3], S2, ec.w);
        __half2 h0 = __floats2half2_rn(sx, sy);
        __half2 h1 = __floats2half2_rn(sz, sw);
        uint2 u;
        u.x = *(const uint32_t*)&h0;
        u.y = *(const uint32_t*)&h1;
        *(uint2*)(g_scores16 + (size_t)(bm + row) * KC + bn + c4) = u;
    }
}

// ---------------------------------------------------------------------------
// Kernel 3: per-row argmax (+ exact fp32 rescue, scan BEFORE exp — keeps regs
// at 128) + softmax (p = 2^(v'-m')) + class-prob partials + outputs.
// ---------------------------------------------------------------------------
__global__ __launch_bounds__(128) void row_kernel(const float* __restrict__ x,
                                                  const float* __restrict__ embed,
                                                  float* __restrict__ out,
                                                  int m0) {
    __shared__ float cp[4][KC];
    __shared__ int s_cnt[4];
    __shared__ int s_list[4][32];
    const int tid = threadIdx.x;
    const int warp = tid >> 5, lane = tid & 31;

    for (int i = tid; i < 4 * KC; i += 128) (&cp[0][0])[i] = 0.f;
    __syncthreads();

    const int row0 = m0 + blockIdx.x * 32;
    float* cpw = cp[warp];

    for (int it = 0; it < 8; it++) {
        const int row = row0 + warp * 8 + it;
        const __half* S = g_scores16 + (size_t)row * KC;

        float v[64];
        float m = -CUDART_INF_F;
        int mi = 0;
#pragma unroll
        for (int j = 0; j < 8; j++) {
            const int kbase = j * 256 + lane * 8;
            const uint4 qq = *(const uint4*)(S + kbase);
            const float2 f0 = __half22float2(*(const __half2*)&qq.x);
            const float2 f1 = __half22float2(*(const __half2*)&qq.y);
            const float2 f2 = __half22float2(*(const __half2*)&qq.z);
            const float2 f3 = __half22float2(*(const __half2*)&qq.w);
            v[8 * j + 0] = f0.x; v[8 * j + 1] = f0.y;
            v[8 * j + 2] = f1.x; v[8 * j + 3] = f1.y;
            v[8 * j + 4] = f2.x; v[8 * j + 5] = f2.y;
            v[8 * j + 6] = f3.x; v[8 * j + 7] = f3.y;
#pragma unroll
            for (int q = 0; q < 8; q++)
                if (v[8 * j + q] > m) { m = v[8 * j + q]; mi = kbase + q; }
        }
#pragma unroll
        for (int off = 16; off > 0; off >>= 1) {
            float om = __shfl_xor_sync(0xffffffffu, m, off);
            int oi = __shfl_xor_sync(0xffffffffu, mi, off);
            if (om > m || (om == m && oi < mi)) { m = om; mi = oi; }
        }

        // Candidate detection for exact rescue (R10 ordering: on raw scores).
        const float thr = m - RESCUE_THR_S;
        int cnt = 0;
#pragma unroll
        for (int j = 0; j < 64; j++) cnt += (v[j] > thr) ? 1 : 0;
#pragma unroll
        for (int off = 16; off > 0; off >>= 1)
            cnt += __shfl_xor_sync(0xffffffffu, cnt, off);

        if (cnt > 1) {
            if (lane == 0) s_cnt[warp] = 0;
            __syncwarp();
#pragma unroll
            for (int j = 0; j < 64; j++) {
                if (v[j] > thr) {
                    int pos = atomicAdd(&s_cnt[warp], 1);
                    if (pos < 32)
                        s_list[warp][pos] = (j >> 3) * 256 + lane * 8 + (j & 7);
                }
            }
            __syncwarp();
            const int nc = min(s_cnt[warp], 32);
            const float4 xa = *(const float4*)(x + (size_t)row * D + lane * 4);
            float bv = -CUDART_INF_F; int bi = 0x7fffffff;
            for (int t = 0; t < nc; t++) {
                const int cidx = s_list[warp][t];
                const float4 ea = *(const float4*)(embed + (size_t)cidx * D + lane * 4);
                float d = xa.x * ea.x + xa.y * ea.y + xa.z * ea.z + xa.w * ea.w;
#pragma unroll
                for (int off = 16; off > 0; off >>= 1)
                    d += __shfl_xor_sync(0xffffffffu, d, off);
                const float sc = 2.f * d - g_esq[cidx];
                if (sc > bv || (sc == bv && cidx < bi)) { bv = sc; bi = cidx; }
            }
            mi = bi;
        }

        // softmax: p = 2^(v - m); temperature+log2e pre-folded into scores
        float s = 0.f;
#pragma unroll
        for (int j = 0; j < 64; j++) {
            float e = ex2f(v[j] - m);
            v[j] = e;
            s += e;
        }
#pragma unroll
        for (int off = 16; off > 0; off >>= 1)
            s += __shfl_xor_sync(0xffffffffu, s, off);
        const float inv = 1.f / s;

#pragma unroll
        for (int j = 0; j < 8; j++) {
            float4* p0 = (float4*)(cpw + j * 256 + lane * 8);
            float4 c0 = p0[0];
            c0.x += v[8 * j + 0] * inv; c0.y += v[8 * j + 1] * inv;
            c0.z += v[8 * j + 2] * inv; c0.w += v[8 * j + 3] * inv;
            p0[0] = c0;
            float4 c1 = p0[1];
            c1.x += v[8 * j + 4] * inv; c1.y += v[8 * j + 5] * inv;
            c1.z += v[8 * j + 6] * inv; c1.w += v[8 * j + 7] * inv;
            p0[1] = c1;
        }

        float4 q = *(const float4*)(embed + (size_t)mi * D + lane * 4);
        *(float4*)(out + (size_t)row * D + lane * 4) = q;
        if (lane == 0) out[(size_t)NP * D + row] = (float)mi;
    }

    __syncthreads();
    const int pb = (m0 >> 5) + blockIdx.x;
    for (int i = tid; i < KC; i += 128)
        g_part[(size_t)pb * KC + i] =
            cp[0][i] + cp[1][i] + cp[2][i] + cp[3][i];
}

// ---------------------------------------------------------------------------
// Kernel 4a/4b: two-stage deterministic reduce of partials
// ---------------------------------------------------------------------------
__global__ __launch_bounds__(256) void reduce1_kernel() {
    const int k = blockIdx.x * 256 + threadIdx.x;
    const int b0 = blockIdx.y * 64;
    float s0 = 0.f, s1 = 0.f, s2 = 0.f, s3 = 0.f;
    for (int b = 0; b < 64; b += 4) {
        s0 += g_part[(size_t)(b0 + b + 0) * KC + k];
        s1 += g_part[(size_t)(b0 + b + 1) * KC + k];
        s2 += g_part[(size_t)(b0 + b + 2) * KC + k];
        s3 += g_part[(size_t)(b0 + b + 3) * KC + k];
    }
    g_part2[blockIdx.y * KC + k] = (s0 + s1) + (s2 + s3);
}

__global__ __launch_bounds__(256) void reduce2_kernel() {
    const int k = blockIdx.x * 256 + threadIdx.x;
    float s = 0.f;
#pragma unroll
    for (int b = 0; b < 16; b++) s += g_part2[b * KC + k];
    g_acc[k] = s;
}

// ---------------------------------------------------------------------------
// Kernel 5: diversity loss
// ---------------------------------------------------------------------------
__global__ __launch_bounds__(256) void loss_kernel(float* __restrict__ out) {
    __shared__ float red[8];
    const int tid = threadIdx.x;
    float t = 0.f;
    for (int k = tid; k < KC; k += 256) {
        float p = g_acc[k] * (1.0f / (float)NP);
        t += p * logf(p + LEPS);
    }
#pragma unroll
    for (int off = 16; off > 0; off >>= 1)
        t += __shfl_xor_sync(0xffffffffu, t, off);
    if ((tid & 31) == 0) red[tid >> 5] = t;
    __syncthreads();
    if (tid < 8) {
        t = red[tid];
#pragma unroll
        for (int off = 4; off > 0; off >>= 1)
            t += __shfl_xor_sync(0x000000ffu, t, off);
        if (tid == 0) out[(size_t)NP * D + NP] = t;
    }
}

// ---------------------------------------------------------------------------
extern "C" void kernel_launch(void* const* d_in, const int* in_sizes, int n_in,
                              void* d_out, int out_size) {
    const float* x = (const float*)d_in[0];
    const float* e = (const float*)d_in[1];
    float* out = (float*)d_out;

    cudaFuncSetAttribute(gemm_kernel, cudaFuncAttributeMaxDynamicSharedMemorySize, GEMM_SMEM);

    split_kernel<<<((NP + KC) * D + 255) / 256, 256>>>(x, e);
    prep_kernel<<<(KC + 255) / 256, 256>>>(e);

    // 2 stripes: each 64 MB score slab stays L2-resident between producer
    // (gemm) and consumer (row).
    for (int st = 0; st < 2; st++) {
        const int m0 = st * STRIPE;
        gemm_kernel<<<dim3(KC / 128, STRIPE / 128), 256, GEMM_SMEM>>>(m0);
        row_kernel<<<STRIPE / 32, 128>>>(x, e, out, m0);
    }

    reduce1_kernel<<<dim3(KC / 256, 16), 256>>>();
    reduce2_kernel<<<KC / 256, 256>>>();
    loss_kernel<<<1, 256>>>(out);
}

// round 13
// speedup vs baseline: 1.1323x; 1.1323x over previous
#include <cuda_runtime.h>
#include <cuda_bf16.h>
#include <cuda_fp16.h>
#include <math_constants.h>
#include <cstdint>

// Problem dims (fixed by setup_inputs)
constexpr int NP = 32768;   // 8*4096 points
constexpr int KC = 2048;    // codebook size
constexpr int D  = 128;     // dim
constexpr float LEPS = 1e-6f;
constexpr float OFFS = 128.0f;        // recenters S ~ -128+-28 to ~0 for fp16 storage
// Scores stored pre-scaled: S' = (S + OFFS) * SCALE, SCALE = log2(e)/T.
// Softmax prob = 2^(v' - m') (one ex2 per element; T and log2e pre-folded).
constexpr float SCALE = 1.4426950408889634f / 0.9f;   // 1.60299449
constexpr float RESCUE_THR_S = 0.5f * SCALE;          // raw 0.5 margin, scaled domain

// Scratch (__device__ globals; no allocation allowed)
__device__ __half g_scores16[(size_t)NP * KC];         // 128 MB score matrix (scaled)
__device__ float g_esq[KC];                            // ||e_k||^2 (exact, for rescue)
__device__ float g_esqc[KC];                           // (OFFS - esq) * SCALE (epilogue)
__device__ __nv_bfloat16 g_Xs[(size_t)NP * 128];       // bf16(x) (8 MB)
__device__ __nv_bfloat16 g_Es[(size_t)KC * 256];       // 2-way bf16 split of embed
__device__ float g_part[(size_t)(NP / 32) * KC];       // per-block class-prob partials
__device__ float g_part2[16 * KC];                     // stage-1 reduced partials
__device__ float g_acc[KC];                            // class sums

// ---------------------------------------------------------------------------
__device__ __forceinline__ uint32_t smem_u32(const void* p) {
    uint32_t a;
    asm("{ .reg .u64 t; cvta.to.shared.u64 t, %1; cvt.u32.u64 %0, t; }" : "=r"(a) : "l"(p));
    return a;
}
__device__ __forceinline__ uint32_t sw128(uint32_t off) { return off ^ ((off >> 3) & 0x70); }
__device__ __forceinline__ float ex2f(float x) {
    float r;
    asm("ex2.approx.f32 %0, %1;" : "=f"(r) : "f"(x));
    return r;
}

__device__ __forceinline__ void cp_async16(uint32_t saddr, const void* gaddr) {
    asm volatile("cp.async.cg.shared.global [%0], [%1], 16;" :: "r"(saddr), "l"(gaddr));
}
#define CP_COMMIT() asm volatile("cp.async.commit_group;" ::: "memory")
#define CP_WAIT(n)  asm volatile("cp.async.wait_group %0;" :: "n"(n) : "memory")

__device__ __forceinline__ void ldm_x4(uint32_t* a, uint32_t addr) {
    asm volatile("ldmatrix.sync.aligned.m8n8.x4.shared.b16 {%0,%1,%2,%3}, [%4];"
                 : "=r"(a[0]), "=r"(a[1]), "=r"(a[2]), "=r"(a[3]) : "r"(addr));
}
__device__ __forceinline__ void mma_bf16(float* c, const uint32_t* a, const uint32_t* b) {
    asm volatile("mma.sync.aligned.m16n8k16.row.col.f32.bf16.bf16.f32 "
                 "{%0,%1,%2,%3}, {%4,%5,%6,%7}, {%8,%9}, {%0,%1,%2,%3};"
                 : "+f"(c[0]), "+f"(c[1]), "+f"(c[2]), "+f"(c[3])
                 : "r"(a[0]), "r"(a[1]), "r"(a[2]), "r"(a[3]), "r"(b[0]), "r"(b[1]));
}

// ---------------------------------------------------------------------------
// Kernel 0: bf16 conversion of x; 2-way bf16 split of embed
// ---------------------------------------------------------------------------
__global__ __launch_bounds__(256) void split_kernel(const float* __restrict__ x,
                                                    const float* __restrict__ e) {
    int i = blockIdx.x * 256 + threadIdx.x;
    if (i < NP * D) {
        g_Xs[i] = __float2bfloat16(x[i]);
    } else {
        int j = i - NP * D;
        if (j >= KC * D) return;
        float v = e[j];
        int c = j & (D - 1);
        __nv_bfloat16* dst = g_Es + (size_t)(j >> 7) * 256;
        __nv_bfloat16 b0 = __float2bfloat16(v);
        float r1 = v - __bfloat162float(b0);
        __nv_bfloat16 b1 = __float2bfloat16(r1);
        dst[c] = b0; dst[128 + c] = b1;
    }
}

// ---------------------------------------------------------------------------
// Kernel 1: e_sq (exact) + scaled epilogue constant
// ---------------------------------------------------------------------------
__global__ void prep_kernel(const float* __restrict__ embed) {
    int k = blockIdx.x * blockDim.x + threadIdx.x;
    if (k < KC) {
        const float4* e = (const float4*)(embed + (size_t)k * D);
        float s = 0.f;
#pragma unroll
        for (int i = 0; i < D / 4; i++) {
            float4 v = e[i];
            s += v.x * v.x + v.y * v.y + v.z * v.z + v.w * v.w;
        }
        g_esq[k] = s;
        g_esqc[k] = (OFFS - s) * SCALE;
    }
}

// ---------------------------------------------------------------------------
// Kernel 2: mma.sync bf16 GEMM  S16 = fp16((2*x0*(e0+e1) - e_sq + OFFS)*SCALE)
// Block 256 thr (8 warps), tile M128 x N128, warp tile 32x64.
// 4 K-chunks of 64 (virtual K=256), 3-stage cp.async, 1 barrier per chunk.
// ---------------------------------------------------------------------------
constexpr int STG_SZ = 128 * 128;                 // 16 KB per operand stage
constexpr int GEMM_SMEM = 3 * 2 * STG_SZ;         // 98304 B (>= 66048 epilogue tile)

__global__ __launch_bounds__(256, 2) void gemm_kernel() {
    extern __shared__ char smem[];
    const uint32_t sb = smem_u32(smem);
    const int tid = threadIdx.x, wid = tid >> 5, lane = tid & 31;
    const int warp_m = wid & 3, warp_n = wid >> 2;
    const int bm = blockIdx.y * 128, bn = blockIdx.x * 128;

    float acc[2][8][4];
#pragma unroll
    for (int mt = 0; mt < 2; mt++)
#pragma unroll
        for (int nt = 0; nt < 8; nt++)
#pragma unroll
            for (int q = 0; q < 4; q++) acc[mt][nt][q] = 0.f;

    const int lr = tid >> 1;                 // rows 0..127 (2 threads/row)
    const int ls0 = (tid & 1) * 4;           // 16B segment base

    // A x4: 16 rows x 32B
    const int arow = warp_m * 32 + (lane & 7) + ((lane >> 3) & 1) * 8;
    const int acol = ((lane >> 4) & 1) * 16;
    // B x4 (two paired 8-row n-tiles)
    const int b_lrow = ((lane >> 4) & 1) * 8 + (lane & 7);
    const int b_lcol = ((lane >> 3) & 1) * 16;

    // chunk c: p = c>>1 selects e0/e1, h = c&1 selects 64-dim half.
    auto issue_chunk = [&](int c, int stage) {
        const int p = c >> 1, h = c & 1;
        const uint32_t sa = sb + stage * 2 * STG_SZ;
        const uint32_t sbB = sa + STG_SZ;
        const __nv_bfloat16* ga = g_Xs + (size_t)(bm + lr) * 128 + h * 64;
        const __nv_bfloat16* gb = g_Es + (size_t)(bn + lr) * 256 + p * 128 + h * 64;
#pragma unroll
        for (int s = 0; s < 4; s++) {
            cp_async16(sa + sw128((uint32_t)lr * 128 + (ls0 + s) * 16), ga + (ls0 + s) * 8);
            cp_async16(sbB + sw128((uint32_t)lr * 128 + (ls0 + s) * 16), gb + (ls0 + s) * 8);
        }
        CP_COMMIT();
    };

    issue_chunk(0, 0);
    issue_chunk(1, 1);

#pragma unroll 1
    for (int c = 0; c < 4; c++) {
        const int stage = c % 3;
        if (c < 3) { CP_WAIT(1); } else { CP_WAIT(0); }
        __syncthreads();

        const uint32_t sa = sb + stage * 2 * STG_SZ;
        const uint32_t sbB = sa + STG_SZ;
#pragma unroll
        for (int ks = 0; ks < 4; ks++) {
            uint32_t a[2][4];
#pragma unroll
            for (int mt = 0; mt < 2; mt++)
                ldm_x4(a[mt], sa + sw128((uint32_t)(arow + mt * 16) * 128 + ks * 32 + acol));
#pragma unroll
            for (int ntp = 0; ntp < 4; ntp++) {
                uint32_t b[4];
                ldm_x4(b, sbB + sw128((uint32_t)(warp_n * 64 + ntp * 16 + b_lrow) * 128
                                       + ks * 32 + b_lcol));
                mma_bf16(acc[0][2 * ntp],     a[0], b);
                mma_bf16(acc[1][2 * ntp],     a[1], b);
                mma_bf16(acc[0][2 * ntp + 1], a[0], b + 2);
                mma_bf16(acc[1][2 * ntp + 1], a[1], b + 2);
            }
        }
        if (c <= 1) issue_chunk(c + 2, (c + 2) % 3);
    }
    __syncthreads();

    // Epilogue: accum -> padded smem tile -> coalesced fp16 scaled scores
    float* tile = (float*)smem;
#pragma unroll
    for (int mt = 0; mt < 2; mt++) {
        const int r = warp_m * 32 + mt * 16 + (lane >> 2);
#pragma unroll
        for (int nt = 0; nt < 8; nt++) {
            const int cb = warp_n * 64 + nt * 8 + 2 * (lane & 3);
            tile[r * 129 + cb]           = acc[mt][nt][0];
            tile[r * 129 + cb + 1]       = acc[mt][nt][1];
            tile[(r + 8) * 129 + cb]     = acc[mt][nt][2];
            tile[(r + 8) * 129 + cb + 1] = acc[mt][nt][3];
        }
    }
    __syncthreads();

    constexpr float S2 = 2.0f * SCALE;
#pragma unroll
    for (int i = 0; i < 16; i++) {
        const int lin = tid + i * 256;           // 0..4095
        const int row = lin >> 5;
        const int c4 = (lin & 31) * 4;
        const float4 ec = *(const float4*)(g_esqc + bn + c4);
        const float sx = fmaf(tile[row * 129 + c4 + 0], S2, ec.x);
        const float sy = fmaf(tile[row * 129 + c4 + 1], S2, ec.y);
        const float sz = fmaf(tile[row * 129 + c4 + 2], S2, ec.z);
        const float sw = fmaf(tile[row * 129 + c4 + 3], S2, ec.w);
        __half2 h0 = __floats2half2_rn(sx, sy);
        __half2 h1 = __floats2half2_rn(sz, sw);
        uint2 u;
        u.x = *(const uint32_t*)&h0;
        u.y = *(const uint32_t*)&h1;
        *(uint2*)(g_scores16 + (size_t)(bm + row) * KC + bn + c4) = u;
    }
}

// ---------------------------------------------------------------------------
// Kernel 3: per-row argmax (+ exact fp32 rescue, scan BEFORE exp) + softmax
// (p = 2^(v'-m')) + class-prob partials + outputs.
// __launch_bounds__(128, 4) pins regs <= 128 (4 blk x 128 thr x 128 = full RF)
// — the R11/R12 register creep is the known failure mode here.
// ---------------------------------------------------------------------------
__global__ __launch_bounds__(128, 4) void row_kernel(const float* __restrict__ x,
                                                     const float* __restrict__ embed,
                                                     float* __restrict__ out) {
    __shared__ float cp[4][KC];
    __shared__ int s_cnt[4];
    __shared__ int s_list[4][32];
    const int tid = threadIdx.x;
    const int warp = tid >> 5, lane = tid & 31;

    for (int i = tid; i < 4 * KC; i += 128) (&cp[0][0])[i] = 0.f;
    __syncthreads();

    const int row0 = blockIdx.x * 32;
    float* cpw = cp[warp];

    for (int it = 0; it < 8; it++) {
        const int row = row0 + warp * 8 + it;
        const __half* S = g_scores16 + (size_t)row * KC;

        float v[64];
        float m = -CUDART_INF_F;
        int mi = 0;
#pragma unroll
        for (int j = 0; j < 8; j++) {
            const int kbase = j * 256 + lane * 8;
            const uint4 qq = *(const uint4*)(S + kbase);
            const float2 f0 = __half22float2(*(const __half2*)&qq.x);
            const float2 f1 = __half22float2(*(const __half2*)&qq.y);
            const float2 f2 = __half22float2(*(const __half2*)&qq.z);
            const float2 f3 = __half22float2(*(const __half2*)&qq.w);
            v[8 * j + 0] = f0.x; v[8 * j + 1] = f0.y;
            v[8 * j + 2] = f1.x; v[8 * j + 3] = f1.y;
            v[8 * j + 4] = f2.x; v[8 * j + 5] = f2.y;
            v[8 * j + 6] = f3.x; v[8 * j + 7] = f3.y;
#pragma unroll
            for (int q = 0; q < 8; q++)
                if (v[8 * j + q] > m) { m = v[8 * j + q]; mi = kbase + q; }
        }
#pragma unroll
        for (int off = 16; off > 0; off >>= 1) {
            float om = __shfl_xor_sync(0xffffffffu, m, off);
            int oi = __shfl_xor_sync(0xffffffffu, mi, off);
            if (om > m || (om == m && oi < mi)) { m = om; mi = oi; }
        }

        // Candidate detection for exact rescue (on raw scaled scores).
        const float thr = m - RESCUE_THR_S;
        int cnt = 0;
#pragma unroll
        for (int j = 0; j < 64; j++) cnt += (v[j] > thr) ? 1 : 0;
#pragma unroll
        for (int off = 16; off > 0; off >>= 1)
            cnt += __shfl_xor_sync(0xffffffffu, cnt, off);

        if (cnt > 1) {
            if (lane == 0) s_cnt[warp] = 0;
            __syncwarp();
#pragma unroll
            for (int j = 0; j < 64; j++) {
                if (v[j] > thr) {
                    int pos = atomicAdd(&s_cnt[warp], 1);
                    if (pos < 32)
                        s_list[warp][pos] = (j >> 3) * 256 + lane * 8 + (j & 7);
                }
            }
            __syncwarp();
            const int nc = min(s_cnt[warp], 32);
            const float4 xa = *(const float4*)(x + (size_t)row * D + lane * 4);
            float bv = -CUDART_INF_F; int bi = 0x7fffffff;
            for (int t = 0; t < nc; t++) {
                const int cidx = s_list[warp][t];
                const float4 ea = *(const float4*)(embed + (size_t)cidx * D + lane * 4);
                float d = xa.x * ea.x + xa.y * ea.y + xa.z * ea.z + xa.w * ea.w;
#pragma unroll
                for (int off = 16; off > 0; off >>= 1)
                    d += __shfl_xor_sync(0xffffffffu, d, off);
                const float sc = 2.f * d - g_esq[cidx];
                if (sc > bv || (sc == bv && cidx < bi)) { bv = sc; bi = cidx; }
            }
            mi = bi;
        }

        // softmax: p = 2^(v - m); temperature+log2e pre-folded into scores
        float s = 0.f;
#pragma unroll
        for (int j = 0; j < 64; j++) {
            float e = ex2f(v[j] - m);
            v[j] = e;
            s += e;
        }
#pragma unroll
        for (int off = 16; off > 0; off >>= 1)
            s += __shfl_xor_sync(0xffffffffu, s, off);
        const float inv = 1.f / s;

#pragma unroll
        for (int j = 0; j < 8; j++) {
            float4* p0 = (float4*)(cpw + j * 256 + lane * 8);
            float4 c0 = p0[0];
            c0.x += v[8 * j + 0] * inv; c0.y += v[8 * j + 1] * inv;
            c0.z += v[8 * j + 2] * inv; c0.w += v[8 * j + 3] * inv;
            p0[0] = c0;
            float4 c1 = p0[1];
            c1.x += v[8 * j + 4] * inv; c1.y += v[8 * j + 5] * inv;
            c1.z += v[8 * j + 6] * inv; c1.w += v[8 * j + 7] * inv;
            p0[1] = c1;
        }

        float4 q = *(const float4*)(embed + (size_t)mi * D + lane * 4);
        *(float4*)(out + (size_t)row * D + lane * 4) = q;
        if (lane == 0) out[(size_t)NP * D + row] = (float)mi;
    }

    __syncthreads();
    for (int i = tid; i < KC; i += 128)
        g_part[(size_t)blockIdx.x * KC + i] =
            cp[0][i] + cp[1][i] + cp[2][i] + cp[3][i];
}

// ---------------------------------------------------------------------------
// Kernel 4a/4b: two-stage deterministic reduce of partials
// ---------------------------------------------------------------------------
__global__ __launch_bounds__(256) void reduce1_kernel() {
    const int k = blockIdx.x * 256 + threadIdx.x;
    const int b0 = blockIdx.y * 64;
    float s0 = 0.f, s1 = 0.f, s2 = 0.f, s3 = 0.f;
    for (int b = 0; b < 64; b += 4) {
        s0 += g_part[(size_t)(b0 + b + 0) * KC + k];
        s1 += g_part[(size_t)(b0 + b + 1) * KC + k];
        s2 += g_part[(size_t)(b0 + b + 2) * KC + k];
        s3 += g_part[(size_t)(b0 + b + 3) * KC + k];
    }
    g_part2[blockIdx.y * KC + k] = (s0 + s1) + (s2 + s3);
}

__global__ __launch_bounds__(256) void reduce2_kernel() {
    const int k = blockIdx.x * 256 + threadIdx.x;
    float s = 0.f;
#pragma unroll
    for (int b = 0; b < 16; b++) s += g_part2[b * KC + k];
    g_acc[k] = s;
}

// ---------------------------------------------------------------------------
// Kernel 5: diversity loss
// ---------------------------------------------------------------------------
__global__ __launch_bounds__(256) void loss_kernel(float* __restrict__ out) {
    __shared__ float red[8];
    const int tid = threadIdx.x;
    float t = 0.f;
    for (int k = tid; k < KC; k += 256) {
        float p = g_acc[k] * (1.0f / (float)NP);
        t += p * logf(p + LEPS);
    }
#pragma unroll
    for (int off = 16; off > 0; off >>= 1)
        t += __shfl_xor_sync(0xffffffffu, t, off);
    if ((tid & 31) == 0) red[tid >> 5] = t;
    __syncthreads();
    if (tid < 8) {
        t = red[tid];
#pragma unroll
        for (int off = 4; off > 0; off >>= 1)
            t += __shfl_xor_sync(0x000000ffu, t, off);
        if (tid == 0) out[(size_t)NP * D + NP] = t;
    }
}

// ---------------------------------------------------------------------------
extern "C" void kernel_launch(void* const* d_in, const int* in_sizes, int n_in,
                              void* d_out, int out_size) {
    const float* x = (const float*)d_in[0];
    const float* e = (const float*)d_in[1];
    float* out = (float*)d_out;

    cudaFuncSetAttribute(gemm_kernel, cudaFuncAttributeMaxDynamicSharedMemorySize, GEMM_SMEM);

    split_kernel<<<((NP + KC) * D + 255) / 256, 256>>>(x, e);
    prep_kernel<<<(KC + 255) / 256, 256>>>(e);
    gemm_kernel<<<dim3(KC / 128, NP / 128), 256, GEMM_SMEM>>>();
    row_kernel<<<NP / 32, 128>>>(x, e, out);
    reduce1_kernel<<<dim3(KC / 256, 16), 256>>>();
    reduce2_kernel<<<KC / 256, 256>>>();
    loss_kernel<<<1, 256>>>(out);
}